// round 16
// baseline (speedup 1.0000x reference)
#include <cuda_runtime.h>
#include <cuda_bf16.h>
#include <cstdint>

#define NSEQ   4096
#define DHEAD  128
#define NSPLIT 8

// ---- GEMM1 tiling: CTA 64x64, BK=32, 3-stage cp.async, 256 threads ----
#define GKDIM 4096
#define NCH   128
#define SROW  80
#define AL_OFF 5120
#define BH_OFF 10240
#define BL_OFF 15360
#define STAGE2 20480
#define GEMM_SMEM (3 * STAGE2)     // 61440 -> 3 CTAs/SM (24 warps/SM)

// ---- attention smem layout (row stride 272B = 128 bf16 + 16B pad) ----
#define RS 272
#define AT_QH   0
#define AT_QL   (128 * RS)
#define AT_BUF0 (2 * 128 * RS)
#define AT_BUFSZ (4 * 64 * RS)
#define KT_KL_D (64 * RS)
#define KT_VH_D (2 * 64 * RS)
#define ATT_SMEM (AT_BUF0 + 2 * AT_BUFSZ)   // 208896

// Scratch (no cudaMalloc allowed)
__device__ __nv_bfloat16 g_xh[(size_t)NSEQ * GKDIM];
__device__ __nv_bfloat16 g_xl[(size_t)NSEQ * GKDIM];
__device__ __nv_bfloat16 g_wh[3 * DHEAD * GKDIM];
__device__ __nv_bfloat16 g_wl[3 * DHEAD * GKDIM];
__device__ __nv_bfloat16 g_qh[NSEQ * DHEAD];
__device__ __nv_bfloat16 g_ql[NSEQ * DHEAD];
__device__ __nv_bfloat16 g_kh[NSEQ * DHEAD];
__device__ __nv_bfloat16 g_kl[NSEQ * DHEAD];
__device__ __nv_bfloat16 g_vh[NSEQ * DHEAD];
__device__ __nv_bfloat16 g_vl[NSEQ * DHEAD];
__device__ float g_opart[NSPLIT * NSEQ * DHEAD];
__device__ float g_mpart[NSPLIT * NSEQ];
__device__ float g_lpart[NSPLIT * NSEQ];

// ---------------------------------------------------------------------------
// helpers
// ---------------------------------------------------------------------------
__device__ __forceinline__ uint32_t smem_u32(const void* p) {
    uint32_t a;
    asm("{ .reg .u64 t; cvta.to.shared.u64 t, %1; cvt.u32.u64 %0, t; }"
        : "=r"(a) : "l"(p));
    return a;
}
__device__ __forceinline__ void ldm4(uint32_t r[4], uint32_t addr) {
    asm volatile("ldmatrix.sync.aligned.m8n8.x4.shared.b16 {%0,%1,%2,%3}, [%4];"
                 : "=r"(r[0]), "=r"(r[1]), "=r"(r[2]), "=r"(r[3]) : "r"(addr));
}
__device__ __forceinline__ void ldm4t(uint32_t r[4], uint32_t addr) {
    asm volatile("ldmatrix.sync.aligned.m8n8.x4.trans.shared.b16 {%0,%1,%2,%3}, [%4];"
                 : "=r"(r[0]), "=r"(r[1]), "=r"(r[2]), "=r"(r[3]) : "r"(addr));
}
__device__ __forceinline__ void mma_bf16(float c[4], uint32_t a0, uint32_t a1,
                                         uint32_t a2, uint32_t a3,
                                         uint32_t b0, uint32_t b1) {
    asm volatile(
        "mma.sync.aligned.m16n8k16.row.col.f32.bf16.bf16.f32 "
        "{%0,%1,%2,%3}, {%4,%5,%6,%7}, {%8,%9}, {%0,%1,%2,%3};"
        : "+f"(c[0]), "+f"(c[1]), "+f"(c[2]), "+f"(c[3])
        : "r"(a0), "r"(a1), "r"(a2), "r"(a3), "r"(b0), "r"(b1));
}
__device__ __forceinline__ void split2(float x, float y, uint32_t& hi, uint32_t& lo) {
    __nv_bfloat16 hx = __float2bfloat16_rn(x);
    __nv_bfloat16 hy = __float2bfloat16_rn(y);
    float rx = x - __bfloat162float(hx);
    float ry = y - __bfloat162float(hy);
    __nv_bfloat162 h; h.x = hx; h.y = hy;
    __nv_bfloat162 l = __floats2bfloat162_rn(rx, ry);
    hi = *(uint32_t*)&h;
    lo = *(uint32_t*)&l;
}
__device__ __forceinline__ void cp16(uint32_t s, const void* g) {
    asm volatile("cp.async.cg.shared.global [%0], [%1], 16;" :: "r"(s), "l"(g));
}
__device__ __forceinline__ void cp_commit() {
    asm volatile("cp.async.commit_group;" ::: "memory");
}
__device__ __forceinline__ void cp_wait1() {
    asm volatile("cp.async.wait_group 1;" ::: "memory");
}
__device__ __forceinline__ void cp_wait0() {
    asm volatile("cp.async.wait_group 0;" ::: "memory");
}
// fast exp on the FMA pipe (deg-5 poly, rel err ~3e-6)
__device__ __forceinline__ float fexp(float x) {
    float y = fmaxf(x * 1.4426950408889634f, -126.0f);
    float n = rintf(y);
    float f = y - n;
    float p =              1.338735821e-3f;
    p = fmaf(p, f, 9.618437357e-3f);
    p = fmaf(p, f, 5.550332471e-2f);
    p = fmaf(p, f, 2.402264476e-1f);
    p = fmaf(p, f, 6.931472028e-1f);
    p = fmaf(p, f, 1.0f);
    return p * __int_as_float(((int)n + 127) << 23);
}

// ---------------------------------------------------------------------------
// Kernel 0: split fp32 -> bf16 hi/lo. which=0 -> x arrays, which=1 -> W arrays.
// ---------------------------------------------------------------------------
__global__ __launch_bounds__(256) void split_kernel(const float4* __restrict__ src,
                                                    int n4, int which) {
    int i = blockIdx.x * 256 + threadIdx.x;
    if (i < n4) {
        uint2* hi = (which == 0) ? (uint2*)g_xh : (uint2*)g_wh;
        uint2* lo = (which == 0) ? (uint2*)g_xl : (uint2*)g_wl;
        float4 v = src[i];
        uint32_t h0, l0, h1, l1;
        split2(v.x, v.y, h0, l0);
        split2(v.z, v.w, h1, l1);
        hi[i] = make_uint2(h0, h1);
        lo[i] = make_uint2(l0, l1);
    }
}

// ---------------------------------------------------------------------------
// Kernel 1: qkv = x @ W^T + b. CTA 64x64, BK=32, 256 threads (8 warps 4Mx2N,
// warp tile 16x32), 3-stage cp.async pipeline. grid (6, 64). 3 CTAs/SM.
// ---------------------------------------------------------------------------
__global__ __launch_bounds__(256, 3) void qkv_mma_kernel(const float* __restrict__ bias) {
    extern __shared__ char sm[];
    const uint32_t sb = smem_u32(sm);
    const int tid  = threadIdx.x;
    const int lane = tid & 31;
    const int wid  = tid >> 5;
    const int wm   = wid & 3;        // 4 M warps, 16 rows each
    const int wn   = wid >> 2;       // 2 N warps, 32 cols each
    const int n0 = blockIdx.x * 64;
    const int m0 = blockIdx.y * 64;

    // producer: 4 arrays (Ah,Al,Bh,Bl) x 64 rows; 1 thread per row per array
    const int arr = tid >> 6;        // 0..3
    const int prow = tid & 63;
    const __nv_bfloat16* psrc0 =
        (arr == 0) ? (g_xh + (size_t)(m0 + prow) * GKDIM) :
        (arr == 1) ? (g_xl + (size_t)(m0 + prow) * GKDIM) :
        (arr == 2) ? (g_wh + (size_t)(n0 + prow) * GKDIM) :
                     (g_wl + (size_t)(n0 + prow) * GKDIM);
    const char* psrc = (const char*)psrc0;
    const uint32_t pdst = sb + arr * 5120 + prow * SROW;

#define STAGE_LOAD(stg, koB)                                     \
    do {                                                         \
        uint32_t d_ = pdst + (stg) * STAGE2;                     \
        cp16(d_,      psrc + (koB));                             \
        cp16(d_ + 16, psrc + (koB) + 16);                        \
        cp16(d_ + 32, psrc + (koB) + 32);                        \
        cp16(d_ + 48, psrc + (koB) + 48);                        \
    } while (0)

    STAGE_LOAD(0, 0);
    cp_commit();
    STAGE_LOAD(1, 64);
    cp_commit();

    float c[4][4];
#pragma unroll
    for (int nt = 0; nt < 4; nt++)
#pragma unroll
        for (int q = 0; q < 4; q++) c[nt][q] = 0.f;

    const int a_lrow = lane & 15;
    const int a_lk   = (lane >> 4) * 16;
    const int b_lrow = (lane & 7) + ((lane >> 4) << 3);
    const int b_lk   = ((lane >> 3) & 1) * 16;
    const uint32_t aBase = sb + (wm * 16 + a_lrow) * SROW + a_lk;
    const uint32_t bBase = sb + BH_OFF + (wn * 32 + b_lrow) * SROW + b_lk;

    int s_cur = 0, s_nxt = 2;
#pragma unroll 1
    for (int t = 0; t < NCH; t++) {
        cp_wait1();
        __syncthreads();
        if (t + 2 < NCH) STAGE_LOAD(s_nxt, (t + 2) * 64);
        cp_commit();                    // empty group at tail keeps wait count valid
        const uint32_t S = s_cur * STAGE2;
        s_cur = (s_cur == 2) ? 0 : s_cur + 1;
        s_nxt = (s_nxt == 2) ? 0 : s_nxt + 1;

#pragma unroll
        for (int ks = 0; ks < 2; ks++) {
            uint32_t ah[4], al[4], bh2[2][4], bl2[2][4];
            {
                const uint32_t ra = aBase + S + ks * 32;
                ldm4(ah, ra);
                ldm4(al, ra + AL_OFF);
            }
#pragma unroll
            for (int nt2 = 0; nt2 < 2; nt2++) {
                const uint32_t rb = bBase + S + nt2 * (16 * SROW) + ks * 32;
                ldm4(bh2[nt2], rb);
                ldm4(bl2[nt2], rb + (BL_OFF - BH_OFF));
            }
#pragma unroll
            for (int nt = 0; nt < 4; nt++) {
                const uint32_t* bh = &bh2[nt >> 1][(nt & 1) * 2];
                const uint32_t* bl = &bl2[nt >> 1][(nt & 1) * 2];
                mma_bf16(c[nt], ah[0], ah[1], ah[2], ah[3], bh[0], bh[1]);
                mma_bf16(c[nt], ah[0], ah[1], ah[2], ah[3], bl[0], bl[1]);
                mma_bf16(c[nt], al[0], al[1], al[2], al[3], bh[0], bh[1]);
            }
        }
    }
#undef STAGE_LOAD

    // ---- epilogue: (C + bias) -> split bf16 hi/lo -> Q/K/V arrays ----
    const int seg = blockIdx.x >> 1;   // 0,1->Q  2,3->K  4,5->V
    __nv_bfloat16* hiA = (seg == 0) ? g_qh : (seg == 1) ? g_kh : g_vh;
    __nv_bfloat16* loA = (seg == 0) ? g_ql : (seg == 1) ? g_kl : g_vl;
    const int mrow = m0 + wm * 16 + (lane >> 2);
#pragma unroll
    for (int nt = 0; nt < 4; nt++) {
        const int ncol = n0 + wn * 32 + nt * 8 + (lane & 3) * 2;
        const int col  = ncol & 127;
        const float b0v = bias[ncol], b1v = bias[ncol + 1];
        uint32_t h01, l01, h23, l23;
        split2(c[nt][0] + b0v, c[nt][1] + b1v, h01, l01);
        split2(c[nt][2] + b0v, c[nt][3] + b1v, h23, l23);
        *(uint32_t*)&hiA[(size_t)mrow * DHEAD + col]       = h01;
        *(uint32_t*)&loA[(size_t)mrow * DHEAD + col]       = l01;
        *(uint32_t*)&hiA[(size_t)(mrow + 8) * DHEAD + col] = h23;
        *(uint32_t*)&loA[(size_t)(mrow + 8) * DHEAD + col] = l23;
    }
}

// ---------------------------------------------------------------------------
// Kernel 2 (R9 known-good, measured 117us): flash attention via mma.sync bf16.
// BM=128 (8 warps x 16 rows), BN=64, NSPLIT K-splits, cp.async double-buffered.
// grid (32, NSPLIT), 256 threads.
// ---------------------------------------------------------------------------
__global__ __launch_bounds__(256) void attn_mma_kernel() {
    extern __shared__ char sm[];
    const uint32_t sb = smem_u32(sm);
    const int tid  = threadIdx.x;
    const int lane = tid & 31;
    const int wid  = tid >> 5;
    const int qb    = blockIdx.x * 128;
    const int split = blockIdx.y;
    const int kb0   = split * (NSEQ / NSPLIT);

    {
        const __nv_bfloat16* src = (tid < 128) ? g_qh : g_ql;
        const int r = tid & 127;
        uint32_t dst = sb + ((tid < 128) ? AT_QH : AT_QL) + r * RS;
        const char* gp = (const char*)&src[(size_t)(qb + r) * DHEAD];
#pragma unroll
        for (int j = 0; j < 16; j++) cp16(dst + j * 16, gp + j * 16);
    }
    const int kv_a = tid >> 6;
    const int kv_r = tid & 63;
    const __nv_bfloat16* kv_src = (kv_a == 0) ? g_kh : (kv_a == 1) ? g_kl
                                 : (kv_a == 2) ? g_vh : g_vl;
    const uint32_t kv_dst0 = sb + AT_BUF0 + kv_a * (64 * RS) + kv_r * RS;

    {
        const char* gp = (const char*)&kv_src[(size_t)(kb0 + kv_r) * DHEAD];
#pragma unroll
        for (int j = 0; j < 16; j++) cp16(kv_dst0 + j * 16, gp + j * 16);
        cp_commit();
    }

    const int r4 = lane >> 2;
    const int c2 = lane & 3;
    const int wr = wid * 16;
    const uint32_t q_base  = sb + AT_QH + (wr + (lane & 15)) * RS + (lane >> 4) * 16;
    const int b_lrow = (lane & 7) + ((lane >> 4) << 3);
    const int b_lk   = ((lane >> 3) & 1) * 16;

    float m0 = -1e30f, m1 = -1e30f, l0 = 0.f, l1 = 0.f;
    float o[16][4];
#pragma unroll
    for (int nt = 0; nt < 16; nt++)
#pragma unroll
        for (int q = 0; q < 4; q++) o[nt][q] = 0.f;

    const int NTILE = (NSEQ / NSPLIT) / 64;

#pragma unroll 1
    for (int t = 0; t < NTILE; t++) {
        const int buf = t & 1;
        if (t + 1 < NTILE) {
            const uint32_t dst = kv_dst0 + ((t + 1) & 1) * AT_BUFSZ;
            const char* gp = (const char*)&kv_src[(size_t)(kb0 + (t + 1) * 64 + kv_r) * DHEAD];
#pragma unroll
            for (int j = 0; j < 16; j++) cp16(dst + j * 16, gp + j * 16);
            cp_commit();
            cp_wait1();
        } else {
            cp_wait0();
        }
        __syncthreads();

        const uint32_t kbufb = sb + AT_BUF0 + buf * AT_BUFSZ;

        float s[8][4];
#pragma unroll
        for (int nt = 0; nt < 8; nt++)
#pragma unroll
            for (int q = 0; q < 4; q++) s[nt][q] = 0.f;

#pragma unroll
        for (int ks = 0; ks < 8; ks++) {
            uint32_t qh[4], ql[4];
            ldm4(qh, q_base + ks * 32);
            ldm4(ql, q_base + AT_QL + ks * 32);
#pragma unroll
            for (int kp = 0; kp < 4; kp++) {
                uint32_t khf[4], klf[4];
                const uint32_t ka = kbufb + (kp * 16 + b_lrow) * RS + b_lk + ks * 32;
                ldm4(khf, ka);
                ldm4(klf, ka + KT_KL_D);
                mma_bf16(s[2*kp],   qh[0], qh[1], qh[2], qh[3], khf[0], khf[1]);
                mma_bf16(s[2*kp],   qh[0], qh[1], qh[2], qh[3], klf[0], klf[1]);
                mma_bf16(s[2*kp],   ql[0], ql[1], ql[2], ql[3], khf[0], khf[1]);
                mma_bf16(s[2*kp+1], qh[0], qh[1], qh[2], qh[3], khf[2], khf[3]);
                mma_bf16(s[2*kp+1], qh[0], qh[1], qh[2], qh[3], klf[2], klf[3]);
                mma_bf16(s[2*kp+1], ql[0], ql[1], ql[2], ql[3], khf[2], khf[3]);
            }
        }

        float mr0 = -1e30f, mr1 = -1e30f;
#pragma unroll
        for (int nt = 0; nt < 8; nt++) {
            mr0 = fmaxf(mr0, fmaxf(s[nt][0], s[nt][1]));
            mr1 = fmaxf(mr1, fmaxf(s[nt][2], s[nt][3]));
        }
        mr0 = fmaxf(mr0, __shfl_xor_sync(0xffffffffu, mr0, 1));
        mr0 = fmaxf(mr0, __shfl_xor_sync(0xffffffffu, mr0, 2));
        mr1 = fmaxf(mr1, __shfl_xor_sync(0xffffffffu, mr1, 1));
        mr1 = fmaxf(mr1, __shfl_xor_sync(0xffffffffu, mr1, 2));
        const float mn0 = fmaxf(m0, mr0);
        const float mn1 = fmaxf(m1, mr1);
        const float sc0 = fexp(m0 - mn0);
        const float sc1 = fexp(m1 - mn1);
        m0 = mn0; m1 = mn1;

        float rs0 = 0.f, rs1 = 0.f;
        uint32_t phv[8][2], plv[8][2];
#pragma unroll
        for (int nt = 0; nt < 8; nt++) {
            float p00 = fexp(s[nt][0] - mn0);
            float p01 = fexp(s[nt][1] - mn0);
            float p10 = fexp(s[nt][2] - mn1);
            float p11 = fexp(s[nt][3] - mn1);
            rs0 += p00 + p01;
            rs1 += p10 + p11;
            split2(p00, p01, phv[nt][0], plv[nt][0]);
            split2(p10, p11, phv[nt][1], plv[nt][1]);
        }
        rs0 += __shfl_xor_sync(0xffffffffu, rs0, 1);
        rs0 += __shfl_xor_sync(0xffffffffu, rs0, 2);
        rs1 += __shfl_xor_sync(0xffffffffu, rs1, 1);
        rs1 += __shfl_xor_sync(0xffffffffu, rs1, 2);
        l0 = l0 * sc0 + rs0;
        l1 = l1 * sc1 + rs1;
#pragma unroll
        for (int nt = 0; nt < 16; nt++) {
            o[nt][0] *= sc0; o[nt][1] *= sc0;
            o[nt][2] *= sc1; o[nt][3] *= sc1;
        }

        const uint32_t v_base = kbufb + KT_VH_D + (lane & 15) * RS + (lane >> 4) * 16;
#pragma unroll
        for (int kp = 0; kp < 4; kp++) {
            const uint32_t ah0 = phv[2*kp][0], ah1 = phv[2*kp][1];
            const uint32_t ah2 = phv[2*kp+1][0], ah3 = phv[2*kp+1][1];
            const uint32_t al0 = plv[2*kp][0], al1 = plv[2*kp][1];
            const uint32_t al2 = plv[2*kp+1][0], al3 = plv[2*kp+1][1];
#pragma unroll
            for (int dn = 0; dn < 8; dn++) {
                uint32_t vh4[4], vl4[4];
                const uint32_t va = v_base + kp * 16 * RS + dn * 32;
                ldm4t(vh4, va);
                ldm4t(vl4, va + KT_KL_D);
                mma_bf16(o[2*dn],   ah0, ah1, ah2, ah3, vh4[0], vh4[1]);
                mma_bf16(o[2*dn],   ah0, ah1, ah2, ah3, vl4[0], vl4[1]);
                mma_bf16(o[2*dn],   al0, al1, al2, al3, vh4[0], vh4[1]);
                mma_bf16(o[2*dn+1], ah0, ah1, ah2, ah3, vh4[2], vh4[3]);
                mma_bf16(o[2*dn+1], ah0, ah1, ah2, ah3, vl4[2], vl4[3]);
                mma_bf16(o[2*dn+1], al0, al1, al2, al3, vh4[2], vh4[3]);
            }
        }
        __syncthreads();
    }

    const int r0 = qb + wr + r4;
    const int r1 = r0 + 8;
    const size_t base0 = ((size_t)split * NSEQ + r0) * DHEAD;
    const size_t base1 = ((size_t)split * NSEQ + r1) * DHEAD;
#pragma unroll
    for (int nt = 0; nt < 16; nt++) {
        const int d = nt * 8 + c2 * 2;
        *(float2*)&g_opart[base0 + d] = make_float2(o[nt][0], o[nt][1]);
        *(float2*)&g_opart[base1 + d] = make_float2(o[nt][2], o[nt][3]);
    }
    if (c2 == 0) {
        g_mpart[split * NSEQ + r0] = m0;
        g_lpart[split * NSEQ + r0] = l0;
        g_mpart[split * NSEQ + r1] = m1;
        g_lpart[split * NSEQ + r1] = l1;
    }
}

// ---------------------------------------------------------------------------
// Kernel 3: merge NSPLIT splits -> final normalized output
// ---------------------------------------------------------------------------
__global__ __launch_bounds__(256) void combine_kernel(float* __restrict__ out) {
    int idx = blockIdx.x * 256 + threadIdx.x;
    int row = idx >> 5;
    int c   = (idx & 31) << 2;
    float mx = -1e30f;
#pragma unroll
    for (int s = 0; s < NSPLIT; s++) mx = fmaxf(mx, g_mpart[s * NSEQ + row]);
    float den = 0.f;
    float4 acc = make_float4(0.f, 0.f, 0.f, 0.f);
#pragma unroll
    for (int s = 0; s < NSPLIT; s++) {
        float a = __expf(g_mpart[s * NSEQ + row] - mx);
        den += a * g_lpart[s * NSEQ + row];
        float4 ov = *(const float4*)&g_opart[((size_t)s * NSEQ + row) * DHEAD + c];
        acc.x += a * ov.x; acc.y += a * ov.y;
        acc.z += a * ov.z; acc.w += a * ov.w;
    }
    float inv = 1.f / den;
    acc.x *= inv; acc.y *= inv; acc.z *= inv; acc.w *= inv;
    *(float4*)&out[(size_t)row * DHEAD + c] = acc;
}

extern "C" void kernel_launch(void* const* d_in, const int* in_sizes, int n_in,
                              void* d_out, int out_size) {
    const float* x    = (const float*)d_in[0];
    const float* W    = (const float*)d_in[1];
    const float* bias = (const float*)d_in[2];
    float* out = (float*)d_out;

    cudaFuncSetAttribute(qkv_mma_kernel, cudaFuncAttributeMaxDynamicSharedMemorySize, GEMM_SMEM);
    cudaFuncSetAttribute(attn_mma_kernel, cudaFuncAttributeMaxDynamicSharedMemorySize, ATT_SMEM);

    const int n4x = NSEQ * GKDIM / 4;
    const int n4w = 3 * DHEAD * GKDIM / 4;
    split_kernel<<<(n4x + 255) / 256, 256>>>((const float4*)x, n4x, 0);
    split_kernel<<<(n4w + 255) / 256, 256>>>((const float4*)W, n4w, 1);
    qkv_mma_kernel<<<dim3(6, 64), 256, GEMM_SMEM>>>(bias);
    attn_mma_kernel<<<dim3(32, NSPLIT), 256, ATT_SMEM>>>();
    combine_kernel<<<512, 256>>>(out);
}

// round 17
// speedup vs baseline: 1.1820x; 1.1820x over previous
#include <cuda_runtime.h>
#include <cuda_bf16.h>
#include <cstdint>

#define NSEQ   4096
#define DHEAD  128
#define NSPLIT 8

// ---- GEMM1 tiling (R9 known-good): CTA 64x64, BK=32, 3-stage cp.async ----
#define GKDIM 4096
#define NCH   128
#define SROW  80
#define AL_OFF 5120
#define BH_OFF 10240
#define BL_OFF 15360
#define STAGE2 20480
#define GEMM_SMEM (3 * STAGE2)     // 61440 -> 3 CTAs/SM

// ---- attention smem layout (row stride 272B = 128 bf16 + 16B pad) ----
#define RS 272
#define AT_QH   0
#define AT_QL   (128 * RS)
#define AT_BUF0 (2 * 128 * RS)
#define AT_BUFSZ (4 * 64 * RS)
#define KT_KL_D (64 * RS)
#define KT_VH_D (2 * 64 * RS)
#define ATT_SMEM (AT_BUF0 + 2 * AT_BUFSZ)   // 208896

// Scratch (no cudaMalloc allowed)
__device__ __nv_bfloat16 g_xh[(size_t)NSEQ * GKDIM];
__device__ __nv_bfloat16 g_xl[(size_t)NSEQ * GKDIM];
__device__ __nv_bfloat16 g_wh[3 * DHEAD * GKDIM];
__device__ __nv_bfloat16 g_wl[3 * DHEAD * GKDIM];
__device__ __nv_bfloat16 g_qh[NSEQ * DHEAD];
__device__ __nv_bfloat16 g_ql[NSEQ * DHEAD];
__device__ __nv_bfloat16 g_kh[NSEQ * DHEAD];
__device__ __nv_bfloat16 g_kl[NSEQ * DHEAD];
__device__ __nv_bfloat16 g_vh[NSEQ * DHEAD];
__device__ __nv_bfloat16 g_vl[NSEQ * DHEAD];
__device__ float g_opart[NSPLIT * NSEQ * DHEAD];
__device__ float g_mpart[NSPLIT * NSEQ];
__device__ float g_lpart[NSPLIT * NSEQ];

// ---------------------------------------------------------------------------
// helpers
// ---------------------------------------------------------------------------
__device__ __forceinline__ uint32_t smem_u32(const void* p) {
    uint32_t a;
    asm("{ .reg .u64 t; cvta.to.shared.u64 t, %1; cvt.u32.u64 %0, t; }"
        : "=r"(a) : "l"(p));
    return a;
}
__device__ __forceinline__ void ldm4(uint32_t r[4], uint32_t addr) {
    asm volatile("ldmatrix.sync.aligned.m8n8.x4.shared.b16 {%0,%1,%2,%3}, [%4];"
                 : "=r"(r[0]), "=r"(r[1]), "=r"(r[2]), "=r"(r[3]) : "r"(addr));
}
__device__ __forceinline__ void ldm4t(uint32_t r[4], uint32_t addr) {
    asm volatile("ldmatrix.sync.aligned.m8n8.x4.trans.shared.b16 {%0,%1,%2,%3}, [%4];"
                 : "=r"(r[0]), "=r"(r[1]), "=r"(r[2]), "=r"(r[3]) : "r"(addr));
}
__device__ __forceinline__ void mma_bf16(float c[4], uint32_t a0, uint32_t a1,
                                         uint32_t a2, uint32_t a3,
                                         uint32_t b0, uint32_t b1) {
    asm volatile(
        "mma.sync.aligned.m16n8k16.row.col.f32.bf16.bf16.f32 "
        "{%0,%1,%2,%3}, {%4,%5,%6,%7}, {%8,%9}, {%0,%1,%2,%3};"
        : "+f"(c[0]), "+f"(c[1]), "+f"(c[2]), "+f"(c[3])
        : "r"(a0), "r"(a1), "r"(a2), "r"(a3), "r"(b0), "r"(b1));
}
__device__ __forceinline__ void split2(float x, float y, uint32_t& hi, uint32_t& lo) {
    __nv_bfloat16 hx = __float2bfloat16_rn(x);
    __nv_bfloat16 hy = __float2bfloat16_rn(y);
    float rx = x - __bfloat162float(hx);
    float ry = y - __bfloat162float(hy);
    __nv_bfloat162 h; h.x = hx; h.y = hy;
    __nv_bfloat162 l = __floats2bfloat162_rn(rx, ry);
    hi = *(uint32_t*)&h;
    lo = *(uint32_t*)&l;
}
__device__ __forceinline__ void cp16(uint32_t s, const void* g) {
    asm volatile("cp.async.cg.shared.global [%0], [%1], 16;" :: "r"(s), "l"(g));
}
__device__ __forceinline__ void cp_commit() {
    asm volatile("cp.async.commit_group;" ::: "memory");
}
__device__ __forceinline__ void cp_wait1() {
    asm volatile("cp.async.wait_group 1;" ::: "memory");
}
__device__ __forceinline__ void cp_wait0() {
    asm volatile("cp.async.wait_group 0;" ::: "memory");
}
// fast exp on the FMA pipe (deg-5 poly, rel err ~3e-6)
__device__ __forceinline__ float fexp(float x) {
    float y = fmaxf(x * 1.4426950408889634f, -126.0f);
    float n = rintf(y);
    float f = y - n;
    float p =              1.338735821e-3f;
    p = fmaf(p, f, 9.618437357e-3f);
    p = fmaf(p, f, 5.550332471e-2f);
    p = fmaf(p, f, 2.402264476e-1f);
    p = fmaf(p, f, 6.931472028e-1f);
    p = fmaf(p, f, 1.0f);
    return p * __int_as_float(((int)n + 127) << 23);
}

// ---------------------------------------------------------------------------
// Kernel 0: split fp32 -> bf16 hi/lo. which=0 -> x arrays, which=1 -> W arrays.
// ---------------------------------------------------------------------------
__global__ __launch_bounds__(256) void split_kernel(const float4* __restrict__ src,
                                                    int n4, int which) {
    int i = blockIdx.x * 256 + threadIdx.x;
    if (i < n4) {
        uint2* hi = (which == 0) ? (uint2*)g_xh : (uint2*)g_wh;
        uint2* lo = (which == 0) ? (uint2*)g_xl : (uint2*)g_wl;
        float4 v = src[i];
        uint32_t h0, l0, h1, l1;
        split2(v.x, v.y, h0, l0);
        split2(v.z, v.w, h1, l1);
        hi[i] = make_uint2(h0, h1);
        lo[i] = make_uint2(l0, l1);
    }
}

// ---------------------------------------------------------------------------
// Kernel 1 (R9 known-good): qkv = x @ W^T + b. CTA 64x64, BK=32, 128 threads,
// 3-stage cp.async pipeline. grid (6, 64).
// ---------------------------------------------------------------------------
__global__ __launch_bounds__(128, 3) void qkv_mma_kernel(const float* __restrict__ bias) {
    extern __shared__ char sm[];
    const uint32_t sb = smem_u32(sm);
    const int tid  = threadIdx.x;
    const int lane = tid & 31;
    const int wid  = tid >> 5;
    const int wm   = wid & 1;
    const int wn   = wid >> 1;
    const int n0 = blockIdx.x * 64;
    const int m0 = blockIdx.y * 64;

    const int pr = tid >> 1;
    const int ph = tid & 1;
    const char* pAh = (const char*)(g_xh + (size_t)(m0 + pr) * GKDIM) + ph * 16;
    const char* pAl = (const char*)(g_xl + (size_t)(m0 + pr) * GKDIM) + ph * 16;
    const char* pBh = (const char*)(g_wh + (size_t)(n0 + pr) * GKDIM) + ph * 16;
    const char* pBl = (const char*)(g_wl + (size_t)(n0 + pr) * GKDIM) + ph * 16;
    const uint32_t sdst = sb + pr * SROW + ph * 16;

#define STAGE_LOAD(stg, koB)                                     \
    do {                                                         \
        uint32_t d_ = sdst + (stg) * STAGE2;                     \
        cp16(d_,               pAh + (koB));                     \
        cp16(d_ + 32,          pAh + (koB) + 32);                \
        cp16(d_ + AL_OFF,      pAl + (koB));                     \
        cp16(d_ + AL_OFF + 32, pAl + (koB) + 32);                \
        cp16(d_ + BH_OFF,      pBh + (koB));                     \
        cp16(d_ + BH_OFF + 32, pBh + (koB) + 32);                \
        cp16(d_ + BL_OFF,      pBl + (koB));                     \
        cp16(d_ + BL_OFF + 32, pBl + (koB) + 32);                \
    } while (0)

    STAGE_LOAD(0, 0);
    cp_commit();
    STAGE_LOAD(1, 64);
    cp_commit();

    float c[2][4][4];
#pragma unroll
    for (int mt = 0; mt < 2; mt++)
#pragma unroll
        for (int nt = 0; nt < 4; nt++)
#pragma unroll
            for (int q = 0; q < 4; q++) c[mt][nt][q] = 0.f;

    const int a_lrow = lane & 15;
    const int a_lk   = (lane >> 4) * 16;
    const int b_lrow = (lane & 7) + ((lane >> 4) << 3);
    const int b_lk   = ((lane >> 3) & 1) * 16;
    const uint32_t aBase = sb + (wm * 32 + a_lrow) * SROW + a_lk;
    const uint32_t bBase = sb + BH_OFF + (wn * 32 + b_lrow) * SROW + b_lk;

    int s_cur = 0, s_nxt = 2;
#pragma unroll 1
    for (int t = 0; t < NCH; t++) {
        cp_wait1();
        __syncthreads();
        if (t + 2 < NCH) STAGE_LOAD(s_nxt, (t + 2) * 64);
        cp_commit();
        const uint32_t S = s_cur * STAGE2;
        s_cur = (s_cur == 2) ? 0 : s_cur + 1;
        s_nxt = (s_nxt == 2) ? 0 : s_nxt + 1;

#pragma unroll
        for (int ks = 0; ks < 2; ks++) {
            uint32_t ah[2][4], al[2][4], bh2[2][4], bl2[2][4];
#pragma unroll
            for (int mt = 0; mt < 2; mt++) {
                const uint32_t ra = aBase + S + mt * (16 * SROW) + ks * 32;
                ldm4(ah[mt], ra);
                ldm4(al[mt], ra + AL_OFF);
            }
#pragma unroll
            for (int nt2 = 0; nt2 < 2; nt2++) {
                const uint32_t rb = bBase + S + nt2 * (16 * SROW) + ks * 32;
                ldm4(bh2[nt2], rb);
                ldm4(bl2[nt2], rb + (BL_OFF - BH_OFF));
            }
#pragma unroll
            for (int mt = 0; mt < 2; mt++)
#pragma unroll
                for (int nt = 0; nt < 4; nt++) {
                    const uint32_t* bh = &bh2[nt >> 1][(nt & 1) * 2];
                    const uint32_t* bl = &bl2[nt >> 1][(nt & 1) * 2];
                    mma_bf16(c[mt][nt], ah[mt][0], ah[mt][1], ah[mt][2], ah[mt][3], bh[0], bh[1]);
                    mma_bf16(c[mt][nt], ah[mt][0], ah[mt][1], ah[mt][2], ah[mt][3], bl[0], bl[1]);
                    mma_bf16(c[mt][nt], al[mt][0], al[mt][1], al[mt][2], al[mt][3], bh[0], bh[1]);
                }
        }
    }
#undef STAGE_LOAD

    const int seg = blockIdx.x >> 1;
    __nv_bfloat16* hiA = (seg == 0) ? g_qh : (seg == 1) ? g_kh : g_vh;
    __nv_bfloat16* loA = (seg == 0) ? g_ql : (seg == 1) ? g_kl : g_vl;
#pragma unroll
    for (int mt = 0; mt < 2; mt++) {
        const int mrow = m0 + wm * 32 + mt * 16 + (lane >> 2);
#pragma unroll
        for (int nt = 0; nt < 4; nt++) {
            const int ncol = n0 + wn * 32 + nt * 8 + (lane & 3) * 2;
            const int col  = ncol & 127;
            const float b0v = bias[ncol], b1v = bias[ncol + 1];
            uint32_t h01, l01, h23, l23;
            split2(c[mt][nt][0] + b0v, c[mt][nt][1] + b1v, h01, l01);
            split2(c[mt][nt][2] + b0v, c[mt][nt][3] + b1v, h23, l23);
            *(uint32_t*)&hiA[(size_t)mrow * DHEAD + col]       = h01;
            *(uint32_t*)&loA[(size_t)mrow * DHEAD + col]       = l01;
            *(uint32_t*)&hiA[(size_t)(mrow + 8) * DHEAD + col] = h23;
            *(uint32_t*)&loA[(size_t)(mrow + 8) * DHEAD + col] = l23;
        }
    }
}

// ---------------------------------------------------------------------------
// Kernel 2: flash attention (R9 structure) + Q fragments hoisted to registers.
// BM=128 (8 warps x 16 rows), BN=64, NSPLIT K-splits, cp.async double-buffered.
// grid (32, NSPLIT), 256 threads.
// ---------------------------------------------------------------------------
__global__ __launch_bounds__(256) void attn_mma_kernel() {
    extern __shared__ char sm[];
    const uint32_t sb = smem_u32(sm);
    const int tid  = threadIdx.x;
    const int lane = tid & 31;
    const int wid  = tid >> 5;
    const int qb    = blockIdx.x * 128;
    const int split = blockIdx.y;
    const int kb0   = split * (NSEQ / NSPLIT);

    {
        const __nv_bfloat16* src = (tid < 128) ? g_qh : g_ql;
        const int r = tid & 127;
        uint32_t dst = sb + ((tid < 128) ? AT_QH : AT_QL) + r * RS;
        const char* gp = (const char*)&src[(size_t)(qb + r) * DHEAD];
#pragma unroll
        for (int j = 0; j < 16; j++) cp16(dst + j * 16, gp + j * 16);
    }
    const int kv_a = tid >> 6;
    const int kv_r = tid & 63;
    const __nv_bfloat16* kv_src = (kv_a == 0) ? g_kh : (kv_a == 1) ? g_kl
                                 : (kv_a == 2) ? g_vh : g_vl;
    const uint32_t kv_dst0 = sb + AT_BUF0 + kv_a * (64 * RS) + kv_r * RS;

    {
        const char* gp = (const char*)&kv_src[(size_t)(kb0 + kv_r) * DHEAD];
#pragma unroll
        for (int j = 0; j < 16; j++) cp16(kv_dst0 + j * 16, gp + j * 16);
        cp_commit();
    }

    const int r4 = lane >> 2;
    const int c2 = lane & 3;
    const int wr = wid * 16;
    const uint32_t q_base  = sb + AT_QH + (wr + (lane & 15)) * RS + (lane >> 4) * 16;
    const int b_lrow = (lane & 7) + ((lane >> 4) << 3);
    const int b_lk   = ((lane >> 3) & 1) * 16;

    // ---- hoist Q fragments into registers (reused across all key tiles) ----
    cp_wait0();
    __syncthreads();
    uint32_t qfh[8][4], qfl[8][4];
#pragma unroll
    for (int ks = 0; ks < 8; ks++) {
        ldm4(qfh[ks], q_base + ks * 32);
        ldm4(qfl[ks], q_base + AT_QL + ks * 32);
    }

    float m0 = -1e30f, m1 = -1e30f, l0 = 0.f, l1 = 0.f;
    float o[16][4];
#pragma unroll
    for (int nt = 0; nt < 16; nt++)
#pragma unroll
        for (int q = 0; q < 4; q++) o[nt][q] = 0.f;

    const int NTILE = (NSEQ / NSPLIT) / 64;

#pragma unroll 1
    for (int t = 0; t < NTILE; t++) {
        const int buf = t & 1;
        if (t + 1 < NTILE) {
            const uint32_t dst = kv_dst0 + ((t + 1) & 1) * AT_BUFSZ;
            const char* gp = (const char*)&kv_src[(size_t)(kb0 + (t + 1) * 64 + kv_r) * DHEAD];
#pragma unroll
            for (int j = 0; j < 16; j++) cp16(dst + j * 16, gp + j * 16);
            cp_commit();
            cp_wait1();
        } else {
            cp_wait0();
        }
        __syncthreads();

        const uint32_t kbufb = sb + AT_BUF0 + buf * AT_BUFSZ;

        float s[8][4];
#pragma unroll
        for (int nt = 0; nt < 8; nt++)
#pragma unroll
            for (int q = 0; q < 4; q++) s[nt][q] = 0.f;

#pragma unroll
        for (int ks = 0; ks < 8; ks++) {
#pragma unroll
            for (int kp = 0; kp < 4; kp++) {
                uint32_t khf[4], klf[4];
                const uint32_t ka = kbufb + (kp * 16 + b_lrow) * RS + b_lk + ks * 32;
                ldm4(khf, ka);
                ldm4(klf, ka + KT_KL_D);
                mma_bf16(s[2*kp],   qfh[ks][0], qfh[ks][1], qfh[ks][2], qfh[ks][3], khf[0], khf[1]);
                mma_bf16(s[2*kp],   qfh[ks][0], qfh[ks][1], qfh[ks][2], qfh[ks][3], klf[0], klf[1]);
                mma_bf16(s[2*kp],   qfl[ks][0], qfl[ks][1], qfl[ks][2], qfl[ks][3], khf[0], khf[1]);
                mma_bf16(s[2*kp+1], qfh[ks][0], qfh[ks][1], qfh[ks][2], qfh[ks][3], khf[2], khf[3]);
                mma_bf16(s[2*kp+1], qfh[ks][0], qfh[ks][1], qfh[ks][2], qfh[ks][3], klf[2], klf[3]);
                mma_bf16(s[2*kp+1], qfl[ks][0], qfl[ks][1], qfl[ks][2], qfl[ks][3], khf[2], khf[3]);
            }
        }

        float mr0 = -1e30f, mr1 = -1e30f;
#pragma unroll
        for (int nt = 0; nt < 8; nt++) {
            mr0 = fmaxf(mr0, fmaxf(s[nt][0], s[nt][1]));
            mr1 = fmaxf(mr1, fmaxf(s[nt][2], s[nt][3]));
        }
        mr0 = fmaxf(mr0, __shfl_xor_sync(0xffffffffu, mr0, 1));
        mr0 = fmaxf(mr0, __shfl_xor_sync(0xffffffffu, mr0, 2));
        mr1 = fmaxf(mr1, __shfl_xor_sync(0xffffffffu, mr1, 1));
        mr1 = fmaxf(mr1, __shfl_xor_sync(0xffffffffu, mr1, 2));
        const float mn0 = fmaxf(m0, mr0);
        const float mn1 = fmaxf(m1, mr1);
        const float sc0 = fexp(m0 - mn0);
        const float sc1 = fexp(m1 - mn1);
        m0 = mn0; m1 = mn1;

        float rs0 = 0.f, rs1 = 0.f;
        uint32_t phv[8][2], plv[8][2];
#pragma unroll
        for (int nt = 0; nt < 8; nt++) {
            float p00 = fexp(s[nt][0] - mn0);
            float p01 = fexp(s[nt][1] - mn0);
            float p10 = fexp(s[nt][2] - mn1);
            float p11 = fexp(s[nt][3] - mn1);
            rs0 += p00 + p01;
            rs1 += p10 + p11;
            split2(p00, p01, phv[nt][0], plv[nt][0]);
            split2(p10, p11, phv[nt][1], plv[nt][1]);
        }
        rs0 += __shfl_xor_sync(0xffffffffu, rs0, 1);
        rs0 += __shfl_xor_sync(0xffffffffu, rs0, 2);
        rs1 += __shfl_xor_sync(0xffffffffu, rs1, 1);
        rs1 += __shfl_xor_sync(0xffffffffu, rs1, 2);
        l0 = l0 * sc0 + rs0;
        l1 = l1 * sc1 + rs1;
#pragma unroll
        for (int nt = 0; nt < 16; nt++) {
            o[nt][0] *= sc0; o[nt][1] *= sc0;
            o[nt][2] *= sc1; o[nt][3] *= sc1;
        }

        const uint32_t v_base = kbufb + KT_VH_D + (lane & 15) * RS + (lane >> 4) * 16;
#pragma unroll
        for (int kp = 0; kp < 4; kp++) {
            const uint32_t ah0 = phv[2*kp][0], ah1 = phv[2*kp][1];
            const uint32_t ah2 = phv[2*kp+1][0], ah3 = phv[2*kp+1][1];
            const uint32_t al0 = plv[2*kp][0], al1 = plv[2*kp][1];
            const uint32_t al2 = plv[2*kp+1][0], al3 = plv[2*kp+1][1];
#pragma unroll
            for (int dn = 0; dn < 8; dn++) {
                uint32_t vh4[4], vl4[4];
                const uint32_t va = v_base + kp * 16 * RS + dn * 32;
                ldm4t(vh4, va);
                ldm4t(vl4, va + KT_KL_D);
                mma_bf16(o[2*dn],   ah0, ah1, ah2, ah3, vh4[0], vh4[1]);
                mma_bf16(o[2*dn],   ah0, ah1, ah2, ah3, vl4[0], vl4[1]);
                mma_bf16(o[2*dn],   al0, al1, al2, al3, vh4[0], vh4[1]);
                mma_bf16(o[2*dn+1], ah0, ah1, ah2, ah3, vh4[2], vh4[3]);
                mma_bf16(o[2*dn+1], ah0, ah1, ah2, ah3, vl4[2], vl4[3]);
                mma_bf16(o[2*dn+1], al0, al1, al2, al3, vh4[2], vh4[3]);
            }
        }
        __syncthreads();
    }

    const int r0 = qb + wr + r4;
    const int r1 = r0 + 8;
    const size_t base0 = ((size_t)split * NSEQ + r0) * DHEAD;
    const size_t base1 = ((size_t)split * NSEQ + r1) * DHEAD;
#pragma unroll
    for (int nt = 0; nt < 16; nt++) {
        const int d = nt * 8 + c2 * 2;
        *(float2*)&g_opart[base0 + d] = make_float2(o[nt][0], o[nt][1]);
        *(float2*)&g_opart[base1 + d] = make_float2(o[nt][2], o[nt][3]);
    }
    if (c2 == 0) {
        g_mpart[split * NSEQ + r0] = m0;
        g_lpart[split * NSEQ + r0] = l0;
        g_mpart[split * NSEQ + r1] = m1;
        g_lpart[split * NSEQ + r1] = l1;
    }
}

// ---------------------------------------------------------------------------
// Kernel 3: merge NSPLIT splits -> final normalized output
// ---------------------------------------------------------------------------
__global__ __launch_bounds__(256) void combine_kernel(float* __restrict__ out) {
    int idx = blockIdx.x * 256 + threadIdx.x;
    int row = idx >> 5;
    int c   = (idx & 31) << 2;
    float mx = -1e30f;
#pragma unroll
    for (int s = 0; s < NSPLIT; s++) mx = fmaxf(mx, g_mpart[s * NSEQ + row]);
    float den = 0.f;
    float4 acc = make_float4(0.f, 0.f, 0.f, 0.f);
#pragma unroll
    for (int s = 0; s < NSPLIT; s++) {
        float a = __expf(g_mpart[s * NSEQ + row] - mx);
        den += a * g_lpart[s * NSEQ + row];
        float4 ov = *(const float4*)&g_opart[((size_t)s * NSEQ + row) * DHEAD + c];
        acc.x += a * ov.x; acc.y += a * ov.y;
        acc.z += a * ov.z; acc.w += a * ov.w;
    }
    float inv = 1.f / den;
    acc.x *= inv; acc.y *= inv; acc.z *= inv; acc.w *= inv;
    *(float4*)&out[(size_t)row * DHEAD + c] = acc;
}

extern "C" void kernel_launch(void* const* d_in, const int* in_sizes, int n_in,
                              void* d_out, int out_size) {
    const float* x    = (const float*)d_in[0];
    const float* W    = (const float*)d_in[1];
    const float* bias = (const float*)d_in[2];
    float* out = (float*)d_out;

    cudaFuncSetAttribute(qkv_mma_kernel, cudaFuncAttributeMaxDynamicSharedMemorySize, GEMM_SMEM);
    cudaFuncSetAttribute(attn_mma_kernel, cudaFuncAttributeMaxDynamicSharedMemorySize, ATT_SMEM);

    const int n4x = NSEQ * GKDIM / 4;
    const int n4w = 3 * DHEAD * GKDIM / 4;
    split_kernel<<<(n4x + 255) / 256, 256>>>((const float4*)x, n4x, 0);
    split_kernel<<<(n4w + 255) / 256, 256>>>((const float4*)W, n4w, 1);
    qkv_mma_kernel<<<dim3(6, 64), 128, GEMM_SMEM>>>(bias);
    attn_mma_kernel<<<dim3(32, NSPLIT), 256, ATT_SMEM>>>();
    combine_kernel<<<512, 256>>>(out);
}